// round 3
// baseline (speedup 1.0000x reference)
#include <cuda_runtime.h>
#include <cuda_bf16.h>
#include <cstdint>

// Problem constants (fixed by the dataset)
#define NN 100000
#define EE 1600000
#define C  128           // IN_C == OUT_C == 128

// Scratch (no allocations allowed — device globals)
__device__ float g_summed[(size_t)NN * C];   // 51.2 MB accumulator
__device__ float g_deg[NN];

// ---------------------------------------------------------------------------
// Vector reduction helper: one 16B float4 add, no return value (REDG.128)
// ---------------------------------------------------------------------------
__device__ __forceinline__ void red_add_f32x4(float4* addr, float4 v) {
    asm volatile("red.global.add.v4.f32 [%0], {%1, %2, %3, %4};"
                 :: "l"(addr), "f"(v.x), "f"(v.y), "f"(v.z), "f"(v.w)
                 : "memory");
}

// ---------------------------------------------------------------------------
// Kernel 1: zero the accumulator + degree array
// ---------------------------------------------------------------------------
__global__ void zero_kernel() {
    size_t i = (size_t)blockIdx.x * blockDim.x + threadIdx.x;
    const size_t n4 = (size_t)NN * (C / 4);       // 3.2M float4
    if (i < n4) {
        ((float4*)g_summed)[i] = make_float4(0.f, 0.f, 0.f, 0.f);
    }
    if (i < NN) {
        g_deg[i] = 0.f;
    }
}

// ---------------------------------------------------------------------------
// Kernel 2: scatter-add messages. One warp per edge.
// Each lane handles a float4 (32 lanes * 4 floats = 128 channels).
// ---------------------------------------------------------------------------
__global__ __launch_bounds__(256) void scatter_kernel(
    const float* __restrict__ x,
    const int*   __restrict__ edge_row,   // dst
    const int*   __restrict__ edge_col)   // src
{
    int gw   = (int)(((size_t)blockIdx.x * blockDim.x + threadIdx.x) >> 5);
    int lane = threadIdx.x & 31;
    if (gw >= EE) return;

    int d = __ldg(edge_row + gw);
    int s = __ldg(edge_col + gw);

    float4 v = __ldg(((const float4*)x) + (size_t)s * (C / 4) + lane);
    red_add_f32x4(((float4*)g_summed) + (size_t)d * (C / 4) + lane, v);

    if (lane == 0) {
        atomicAdd(g_deg + d, 1.0f);
    }
}

// ---------------------------------------------------------------------------
// Kernel 3: fused  out = relu( (summed/deg) @ W_l  +  x @ W_r  + b_l )
// Block: 256 threads, computes a 64-row x 128-col output tile.
// Two phases share one 128x128 W smem buffer + one 64x128 A smem buffer.
// Register blocking: each thread owns 8 rows x 4 cols.
// ---------------------------------------------------------------------------
__global__ __launch_bounds__(256) void sage_gemm_kernel(
    const float* __restrict__ x,
    const float* __restrict__ W_l,
    const float* __restrict__ b_l,
    const float* __restrict__ W_r,
    float*       __restrict__ out)
{
    extern __shared__ float sm[];
    float* Ws = sm;            // 128*128 = 16384 floats (64 KB)
    float* As = sm + 16384;    //  64*128 =  8192 floats (32 KB)

    const int t     = threadIdx.x;
    const int lane  = t & 31;
    const int warp  = t >> 5;
    const int row0  = blockIdx.x * 64;
    const int rbase = warp * 8;        // 8 rows per warp
    const int cbase = lane * 4;        // 4 cols per lane

    float acc[8][4];
#pragma unroll
    for (int j = 0; j < 8; j++)
#pragma unroll
        for (int c = 0; c < 4; c++) acc[j][c] = 0.f;

    // ================= phase 1: agg @ W_l =================
    {
        // load W_l (128x128 floats = 4096 float4; 16 per thread)
        const float4* Wg  = (const float4*)W_l;
        float4*       Ws4 = (float4*)Ws;
#pragma unroll
        for (int i = 0; i < 16; i++) Ws4[t + i * 256] = __ldg(Wg + t + i * 256);

        // load A tile = summed/deg  (64x128 = 2048 float4; 8 per thread)
#pragma unroll
        for (int i = 0; i < 8; i++) {
            int idx  = t + i * 256;          // float4 index
            int r    = idx >> 5;             // row within tile
            int k4   = idx & 31;             // float4 within row
            int grow = row0 + r;
            float4 v = make_float4(0.f, 0.f, 0.f, 0.f);
            if (grow < NN) {
                float dg  = fmaxf(g_deg[grow], 1.0f);
                float inv = 1.0f / dg;
                float4 s4 = *((const float4*)(g_summed + (size_t)grow * C) + k4);
                v = make_float4(s4.x * inv, s4.y * inv, s4.z * inv, s4.w * inv);
            }
            ((float4*)As)[idx] = v;
        }
        __syncthreads();

#pragma unroll 4
        for (int k = 0; k < 128; k++) {
            float4 w = *((const float4*)(Ws + k * 128) + lane);
#pragma unroll
            for (int j = 0; j < 8; j++) {
                float a = As[(rbase + j) * 128 + k];
                acc[j][0] = fmaf(a, w.x, acc[j][0]);
                acc[j][1] = fmaf(a, w.y, acc[j][1]);
                acc[j][2] = fmaf(a, w.z, acc[j][2]);
                acc[j][3] = fmaf(a, w.w, acc[j][3]);
            }
        }
        __syncthreads();
    }

    // ================= phase 2: x @ W_r =================
    {
        const float4* Wg  = (const float4*)W_r;
        float4*       Ws4 = (float4*)Ws;
#pragma unroll
        for (int i = 0; i < 16; i++) Ws4[t + i * 256] = __ldg(Wg + t + i * 256);

#pragma unroll
        for (int i = 0; i < 8; i++) {
            int idx  = t + i * 256;
            int r    = idx >> 5;
            int k4   = idx & 31;
            int grow = row0 + r;
            float4 v = make_float4(0.f, 0.f, 0.f, 0.f);
            if (grow < NN) {
                v = __ldg((const float4*)(x + (size_t)grow * C) + k4);
            }
            ((float4*)As)[idx] = v;
        }
        __syncthreads();

#pragma unroll 4
        for (int k = 0; k < 128; k++) {
            float4 w = *((const float4*)(Ws + k * 128) + lane);
#pragma unroll
            for (int j = 0; j < 8; j++) {
                float a = As[(rbase + j) * 128 + k];
                acc[j][0] = fmaf(a, w.x, acc[j][0]);
                acc[j][1] = fmaf(a, w.y, acc[j][1]);
                acc[j][2] = fmaf(a, w.z, acc[j][2]);
                acc[j][3] = fmaf(a, w.w, acc[j][3]);
            }
        }
    }

    // ================= epilogue: bias + relu + store =================
    float4 bias = __ldg(((const float4*)b_l) + lane);
#pragma unroll
    for (int j = 0; j < 8; j++) {
        int grow = row0 + rbase + j;
        if (grow < NN) {
            float4 o;
            o.x = fmaxf(acc[j][0] + bias.x, 0.f);
            o.y = fmaxf(acc[j][1] + bias.y, 0.f);
            o.z = fmaxf(acc[j][2] + bias.z, 0.f);
            o.w = fmaxf(acc[j][3] + bias.w, 0.f);
            *((float4*)(out + (size_t)grow * C) + lane) = o;
        }
    }
}

// ---------------------------------------------------------------------------
// Launch
// ---------------------------------------------------------------------------
extern "C" void kernel_launch(void* const* d_in, const int* in_sizes, int n_in,
                              void* d_out, int out_size)
{
    const float* x        = (const float*)d_in[0];
    const int*   edge_row = (const int*)d_in[1];
    const int*   edge_col = (const int*)d_in[2];
    const float* W_l      = (const float*)d_in[3];
    const float* b_l      = (const float*)d_in[4];
    const float* W_r      = (const float*)d_in[5];
    float*       out      = (float*)d_out;

    // 1) zero accumulators: N*32 float4 elements
    {
        size_t n4 = (size_t)NN * (C / 4);
        int blocks = (int)((n4 + 255) / 256);
        zero_kernel<<<blocks, 256>>>();
    }

    // 2) scatter: one warp per edge -> E*32 threads
    {
        size_t threads_total = (size_t)EE * 32;
        int blocks = (int)((threads_total + 255) / 256);
        scatter_kernel<<<blocks, 256>>>(x, edge_row, edge_col);
    }

    // 3) fused GEMM + epilogue
    {
        const int smem_bytes = (16384 + 8192) * sizeof(float);  // 96 KB
        cudaFuncSetAttribute(sage_gemm_kernel,
                             cudaFuncAttributeMaxDynamicSharedMemorySize,
                             smem_bytes);
        int blocks = (NN + 63) / 64;
        sage_gemm_kernel<<<blocks, 256, smem_bytes>>>(x, W_l, b_l, W_r, out);
    }
}

// round 5
// speedup vs baseline: 1.1400x; 1.1400x over previous
#include <cuda_runtime.h>
#include <cuda_bf16.h>
#include <cstdint>

// Problem constants (fixed by the dataset)
#define NN 100000
#define EE 1600000
#define C  128           // IN_C == OUT_C == 128

// Scratch (no allocations allowed — device globals)
__device__ float g_summed[(size_t)NN * C];   // 51.2 MB accumulator
__device__ float g_deg[NN];

// ---------------------------------------------------------------------------
// Helpers
// ---------------------------------------------------------------------------
__device__ __forceinline__ void red_add_f32x4(float4* addr, float4 v) {
    asm volatile("red.global.add.v4.f32 [%0], {%1, %2, %3, %4};"
                 :: "l"(addr), "f"(v.x), "f"(v.y), "f"(v.z), "f"(v.w)
                 : "memory");
}

__device__ __forceinline__ uint32_t f2tf32(float f) {
    uint32_t r;
    asm("cvt.rna.tf32.f32 %0, %1;" : "=r"(r) : "f"(f));
    return r;
}

__device__ __forceinline__ void mma_tf32(float c[4], const uint32_t a[4],
                                         const uint32_t b[2]) {
    asm volatile(
        "mma.sync.aligned.m16n8k8.row.col.f32.tf32.tf32.f32 "
        "{%0,%1,%2,%3}, {%4,%5,%6,%7}, {%8,%9}, {%0,%1,%2,%3};"
        : "+f"(c[0]), "+f"(c[1]), "+f"(c[2]), "+f"(c[3])
        : "r"(a[0]), "r"(a[1]), "r"(a[2]), "r"(a[3]), "r"(b[0]), "r"(b[1]));
}

// ---------------------------------------------------------------------------
// Kernel 1: zero the accumulator + degree array
// ---------------------------------------------------------------------------
__global__ void zero_kernel() {
    size_t i = (size_t)blockIdx.x * blockDim.x + threadIdx.x;
    const size_t n4 = (size_t)NN * (C / 4);       // 3.2M float4
    if (i < n4) {
        ((float4*)g_summed)[i] = make_float4(0.f, 0.f, 0.f, 0.f);
    }
    if (i < NN) {
        g_deg[i] = 0.f;
    }
}

// ---------------------------------------------------------------------------
// Kernel 2: scatter-add messages. One warp per edge.
// ---------------------------------------------------------------------------
__global__ __launch_bounds__(256) void scatter_kernel(
    const float* __restrict__ x,
    const int*   __restrict__ edge_row,   // dst
    const int*   __restrict__ edge_col)   // src
{
    int gw   = (int)(((size_t)blockIdx.x * blockDim.x + threadIdx.x) >> 5);
    int lane = threadIdx.x & 31;
    if (gw >= EE) return;

    int d = __ldg(edge_row + gw);
    int s = __ldg(edge_col + gw);

    float4 v = __ldg(((const float4*)x) + (size_t)s * (C / 4) + lane);
    red_add_f32x4(((float4*)g_summed) + (size_t)d * (C / 4) + lane, v);

    if (lane == 0) {
        atomicAdd(g_deg + d, 1.0f);
    }
}

// ---------------------------------------------------------------------------
// Kernel 3: fused tensor-core GEMM
//   out = relu( (summed/deg) @ W_l  +  x @ W_r  + b_l )
// Equivalent to [agg | x] (K=256) @ [W_l ; W_r].
// CTA: 256 threads (8 warps, 2x4), 128x128 output tile, K in 8 chunks of 32.
// Warp tile 64x32 = 4x4 m16n8k8 tf32 MMAs per k-step.
// Smem stride 36: bank = (4r+c)%32 = laneid -> conflict-free fragment loads.
// ---------------------------------------------------------------------------
#define SM_STRIDE 36

__global__ __launch_bounds__(256) void sage_gemm_kernel(
    const float* __restrict__ x,
    const float* __restrict__ W_l,
    const float* __restrict__ b_l,
    const float* __restrict__ W_r,
    float*       __restrict__ out)
{
    __shared__ uint32_t As[128 * SM_STRIDE];   // A tile   (tf32 bits)
    __shared__ uint32_t Wt[128 * SM_STRIDE];   // W tile, [n][k] transposed
    __shared__ float    sdeg[128];

    const int t      = threadIdx.x;
    const int lane   = t & 31;
    const int warp   = t >> 5;
    const int warp_m = warp >> 2;       // 0..1  -> 64 rows each
    const int warp_n = warp & 3;        // 0..3  -> 32 cols each
    const int row0   = blockIdx.x * 128;

    // Per-row 1/deg
    if (t < 128) {
        int grow = row0 + t;
        sdeg[t] = (grow < NN) ? (1.0f / fmaxf(g_deg[grow], 1.0f)) : 0.0f;
    }
    __syncthreads();

    float acc[4][4][4];
#pragma unroll
    for (int mt = 0; mt < 4; mt++)
#pragma unroll
        for (int nt = 0; nt < 4; nt++)
#pragma unroll
            for (int j = 0; j < 4; j++) acc[mt][nt][j] = 0.f;

#pragma unroll
    for (int kc = 0; kc < 8; kc++) {
        const bool  ph1   = (kc < 4);
        const int   kbase = ph1 ? kc * 32 : (kc - 4) * 32;
        const float* Asrc = ph1 ? g_summed : x;
        const float* Wsrc = ph1 ? W_l : W_r;

        if (kc > 0) __syncthreads();   // protect previous chunk's reads

        // ---- stage A tile: 128 rows x 32 k (1024 float4, 4 per thread) ----
#pragma unroll
        for (int i = 0; i < 4; i++) {
            int f    = t + i * 256;
            int r    = f >> 3;           // row in tile
            int c4   = f & 7;            // float4 within 32-k chunk
            int grow = row0 + r;
            float4 v = make_float4(0.f, 0.f, 0.f, 0.f);
            if (grow < NN) {
                v = __ldg((const float4*)(Asrc + (size_t)grow * C + kbase) + c4);
                if (ph1) {
                    float s = sdeg[r];
                    v.x *= s; v.y *= s; v.z *= s; v.w *= s;
                }
            }
            uint32_t* dst = As + r * SM_STRIDE + c4 * 4;
            dst[0] = f2tf32(v.x); dst[1] = f2tf32(v.y);
            dst[2] = f2tf32(v.z); dst[3] = f2tf32(v.w);
        }

        // ---- stage W tile transposed: Wt[n][k], 32 k x 128 n ----
#pragma unroll
        for (int i = 0; i < 4; i++) {
            int f    = t + i * 256;
            int kloc = f >> 5;           // 0..31
            int n4   = f & 31;           // float4 along n
            float4 w = __ldg((const float4*)(Wsrc + (size_t)(kbase + kloc) * C) + n4);
            Wt[(n4 * 4 + 0) * SM_STRIDE + kloc] = f2tf32(w.x);
            Wt[(n4 * 4 + 1) * SM_STRIDE + kloc] = f2tf32(w.y);
            Wt[(n4 * 4 + 2) * SM_STRIDE + kloc] = f2tf32(w.z);
            Wt[(n4 * 4 + 3) * SM_STRIDE + kloc] = f2tf32(w.w);
        }
        __syncthreads();

        // ---- compute: 4 k-steps of 8 ----
#pragma unroll
        for (int ks = 0; ks < 4; ks++) {
            const int kk = ks * 8;
            uint32_t a[4][4], b[4][2];
#pragma unroll
            for (int mt = 0; mt < 4; mt++) {
                int r = warp_m * 64 + mt * 16 + (lane >> 2);
                int c = kk + (lane & 3);
                a[mt][0] = As[r * SM_STRIDE + c];
                a[mt][1] = As[(r + 8) * SM_STRIDE + c];
                a[mt][2] = As[r * SM_STRIDE + c + 4];
                a[mt][3] = As[(r + 8) * SM_STRIDE + c + 4];
            }
#pragma unroll
            for (int nt = 0; nt < 4; nt++) {
                int n = warp_n * 32 + nt * 8 + (lane >> 2);
                int c = kk + (lane & 3);
                b[nt][0] = Wt[n * SM_STRIDE + c];
                b[nt][1] = Wt[n * SM_STRIDE + c + 4];
            }
#pragma unroll
            for (int mt = 0; mt < 4; mt++)
#pragma unroll
                for (int nt = 0; nt < 4; nt++)
                    mma_tf32(acc[mt][nt], a[mt], b[nt]);
        }
    }

    // ---- epilogue: bias + relu + float2 stores ----
#pragma unroll
    for (int mt = 0; mt < 4; mt++) {
#pragma unroll
        for (int nt = 0; nt < 4; nt++) {
            int r0 = row0 + warp_m * 64 + mt * 16 + (lane >> 2);
            int c0 = warp_n * 32 + nt * 8 + 2 * (lane & 3);
            float2 bias = __ldg((const float2*)(b_l + c0));
            if (r0 < NN) {
                float2 o;
                o.x = fmaxf(acc[mt][nt][0] + bias.x, 0.f);
                o.y = fmaxf(acc[mt][nt][1] + bias.y, 0.f);
                *(float2*)(out + (size_t)r0 * C + c0) = o;
            }
            int r1 = r0 + 8;
            if (r1 < NN) {
                float2 o;
                o.x = fmaxf(acc[mt][nt][2] + bias.x, 0.f);
                o.y = fmaxf(acc[mt][nt][3] + bias.y, 0.f);
                *(float2*)(out + (size_t)r1 * C + c0) = o;
            }
        }
    }
}

// ---------------------------------------------------------------------------
// Launch
// ---------------------------------------------------------------------------
extern "C" void kernel_launch(void* const* d_in, const int* in_sizes, int n_in,
                              void* d_out, int out_size)
{
    const float* x        = (const float*)d_in[0];
    const int*   edge_row = (const int*)d_in[1];
    const int*   edge_col = (const int*)d_in[2];
    const float* W_l      = (const float*)d_in[3];
    const float* b_l      = (const float*)d_in[4];
    const float* W_r      = (const float*)d_in[5];
    float*       out      = (float*)d_out;

    // 1) zero accumulators
    {
        size_t n4 = (size_t)NN * (C / 4);
        int blocks = (int)((n4 + 255) / 256);
        zero_kernel<<<blocks, 256>>>();
    }

    // 2) scatter: one warp per edge
    {
        size_t threads_total = (size_t)EE * 32;
        int blocks = (int)((threads_total + 255) / 256);
        scatter_kernel<<<blocks, 256>>>(x, edge_row, edge_col);
    }

    // 3) fused tensor-core GEMM + epilogue
    {
        int blocks = (NN + 127) / 128;
        sage_gemm_kernel<<<blocks, 256>>>(x, W_l, b_l, W_r, out);
    }
}

// round 6
// speedup vs baseline: 1.4427x; 1.2656x over previous
#include <cuda_runtime.h>
#include <cuda_bf16.h>
#include <cstdint>

// Problem constants (fixed by the dataset)
#define NN 100000
#define EE 1600000
#define C  128           // IN_C == OUT_C == 128
#define CAP 96           // max bucket capacity per node (Poisson(16) tail ~1e-16)

// Scratch (no allocations allowed — device globals)
__device__ float g_agg[(size_t)NN * C];        // 51.2 MB mean-aggregated features
__device__ int   g_cnt[NN];                    // per-node degree counters
__device__ int   g_bucket[(size_t)NN * CAP];   // 38.4 MB src-id buckets

// ---------------------------------------------------------------------------
// Helpers
// ---------------------------------------------------------------------------
__device__ __forceinline__ uint32_t f2tf32(float f) {
    uint32_t r;
    asm("cvt.rna.tf32.f32 %0, %1;" : "=r"(r) : "f"(f));
    return r;
}

__device__ __forceinline__ void mma_tf32(float c[4], const uint32_t a[4],
                                         const uint32_t b[2]) {
    asm volatile(
        "mma.sync.aligned.m16n8k8.row.col.f32.tf32.tf32.f32 "
        "{%0,%1,%2,%3}, {%4,%5,%6,%7}, {%8,%9}, {%0,%1,%2,%3};"
        : "+f"(c[0]), "+f"(c[1]), "+f"(c[2]), "+f"(c[3])
        : "r"(a[0]), "r"(a[1]), "r"(a[2]), "r"(a[3]), "r"(b[0]), "r"(b[1]));
}

// ---------------------------------------------------------------------------
// Kernel 1: zero the per-node counters
// ---------------------------------------------------------------------------
__global__ void zero_cnt_kernel() {
    int i = blockIdx.x * blockDim.x + threadIdx.x;
    if (i < NN) g_cnt[i] = 0;
}

// ---------------------------------------------------------------------------
// Kernel 2: bucket fill. One thread per edge.
// Inverts the edge list: bucket[dst][pos] = src.
// ---------------------------------------------------------------------------
__global__ __launch_bounds__(256) void fill_kernel(
    const int* __restrict__ edge_row,   // dst
    const int* __restrict__ edge_col)   // src
{
    int e = blockIdx.x * blockDim.x + threadIdx.x;
    if (e >= EE) return;
    int d   = __ldg(edge_row + e);
    int s   = __ldg(edge_col + e);
    int pos = atomicAdd(g_cnt + d, 1);
    if (pos < CAP) {
        g_bucket[(size_t)d * CAP + pos] = s;
    }
}

// ---------------------------------------------------------------------------
// Kernel 3: gather-aggregate. One warp per node, each lane owns a float4
// (32 lanes * 4 = 128 channels). 4-way unrolled edge loop for MLP=4.
// Writes mean (sum / max(deg,1)) directly.
// ---------------------------------------------------------------------------
__global__ __launch_bounds__(256) void gather_agg_kernel(
    const float* __restrict__ x)
{
    int warp = (blockIdx.x * blockDim.x + threadIdx.x) >> 5;
    int lane = threadIdx.x & 31;
    if (warp >= NN) return;

    int cnt = g_cnt[warp];
    int deg = min(cnt, CAP);

    const int*    bkt = g_bucket + (size_t)warp * CAP;
    const float4* x4  = (const float4*)x;

    float4 acc = make_float4(0.f, 0.f, 0.f, 0.f);
    int j = 0;
    for (; j + 4 <= deg; j += 4) {
        int s0 = __ldg(bkt + j);
        int s1 = __ldg(bkt + j + 1);
        int s2 = __ldg(bkt + j + 2);
        int s3 = __ldg(bkt + j + 3);
        float4 v0 = __ldg(x4 + (size_t)s0 * 32 + lane);
        float4 v1 = __ldg(x4 + (size_t)s1 * 32 + lane);
        float4 v2 = __ldg(x4 + (size_t)s2 * 32 + lane);
        float4 v3 = __ldg(x4 + (size_t)s3 * 32 + lane);
        acc.x += v0.x + v1.x + v2.x + v3.x;
        acc.y += v0.y + v1.y + v2.y + v3.y;
        acc.z += v0.z + v1.z + v2.z + v3.z;
        acc.w += v0.w + v1.w + v2.w + v3.w;
    }
    for (; j < deg; j++) {
        int s = __ldg(bkt + j);
        float4 v = __ldg(x4 + (size_t)s * 32 + lane);
        acc.x += v.x; acc.y += v.y; acc.z += v.z; acc.w += v.w;
    }

    float inv = 1.0f / fmaxf((float)cnt, 1.0f);
    acc.x *= inv; acc.y *= inv; acc.z *= inv; acc.w *= inv;
    ((float4*)g_agg)[(size_t)warp * 32 + lane] = acc;
}

// ---------------------------------------------------------------------------
// Kernel 4: fused tensor-core GEMM
//   out = relu( agg @ W_l  +  x @ W_r  + b_l )   ==  [agg | x] @ [W_l ; W_r]
// CTA: 256 threads (8 warps, 2x4), 128x128 output tile, K in 8 chunks of 32.
// Warp tile 64x32 = 4x4 m16n8k8 tf32 MMAs per k-step.
// Smem stride 36: bank = (4r+c)%32 = laneid -> conflict-free fragment loads.
// ---------------------------------------------------------------------------
#define SM_STRIDE 36

__global__ __launch_bounds__(256) void sage_gemm_kernel(
    const float* __restrict__ x,
    const float* __restrict__ W_l,
    const float* __restrict__ b_l,
    const float* __restrict__ W_r,
    float*       __restrict__ out)
{
    __shared__ uint32_t As[128 * SM_STRIDE];   // A tile   (tf32 bits)
    __shared__ uint32_t Wt[128 * SM_STRIDE];   // W tile, [n][k] transposed

    const int t      = threadIdx.x;
    const int lane   = t & 31;
    const int warp   = t >> 5;
    const int warp_m = warp >> 2;       // 0..1  -> 64 rows each
    const int warp_n = warp & 3;        // 0..3  -> 32 cols each
    const int row0   = blockIdx.x * 128;

    float acc[4][4][4];
#pragma unroll
    for (int mt = 0; mt < 4; mt++)
#pragma unroll
        for (int nt = 0; nt < 4; nt++)
#pragma unroll
            for (int j = 0; j < 4; j++) acc[mt][nt][j] = 0.f;

#pragma unroll
    for (int kc = 0; kc < 8; kc++) {
        const bool  ph1   = (kc < 4);
        const int   kbase = ph1 ? kc * 32 : (kc - 4) * 32;
        const float* Asrc = ph1 ? g_agg : x;
        const float* Wsrc = ph1 ? W_l : W_r;

        if (kc > 0) __syncthreads();   // protect previous chunk's reads

        // ---- stage A tile: 128 rows x 32 k (1024 float4, 4 per thread) ----
#pragma unroll
        for (int i = 0; i < 4; i++) {
            int f    = t + i * 256;
            int r    = f >> 3;           // row in tile
            int c4   = f & 7;            // float4 within 32-k chunk
            int grow = row0 + r;
            float4 v = make_float4(0.f, 0.f, 0.f, 0.f);
            if (grow < NN) {
                v = __ldg((const float4*)(Asrc + (size_t)grow * C + kbase) + c4);
            }
            uint32_t* dst = As + r * SM_STRIDE + c4 * 4;
            dst[0] = f2tf32(v.x); dst[1] = f2tf32(v.y);
            dst[2] = f2tf32(v.z); dst[3] = f2tf32(v.w);
        }

        // ---- stage W tile transposed: Wt[n][k], 32 k x 128 n ----
#pragma unroll
        for (int i = 0; i < 4; i++) {
            int f    = t + i * 256;
            int kloc = f >> 5;           // 0..31
            int n4   = f & 31;           // float4 along n
            float4 w = __ldg((const float4*)(Wsrc + (size_t)(kbase + kloc) * C) + n4);
            Wt[(n4 * 4 + 0) * SM_STRIDE + kloc] = f2tf32(w.x);
            Wt[(n4 * 4 + 1) * SM_STRIDE + kloc] = f2tf32(w.y);
            Wt[(n4 * 4 + 2) * SM_STRIDE + kloc] = f2tf32(w.z);
            Wt[(n4 * 4 + 3) * SM_STRIDE + kloc] = f2tf32(w.w);
        }
        __syncthreads();

        // ---- compute: 4 k-steps of 8 ----
#pragma unroll
        for (int ks = 0; ks < 4; ks++) {
            const int kk = ks * 8;
            uint32_t a[4][4], b[4][2];
#pragma unroll
            for (int mt = 0; mt < 4; mt++) {
                int r = warp_m * 64 + mt * 16 + (lane >> 2);
                int c = kk + (lane & 3);
                a[mt][0] = As[r * SM_STRIDE + c];
                a[mt][1] = As[(r + 8) * SM_STRIDE + c];
                a[mt][2] = As[r * SM_STRIDE + c + 4];
                a[mt][3] = As[(r + 8) * SM_STRIDE + c + 4];
            }
#pragma unroll
            for (int nt = 0; nt < 4; nt++) {
                int n = warp_n * 32 + nt * 8 + (lane >> 2);
                int c = kk + (lane & 3);
                b[nt][0] = Wt[n * SM_STRIDE + c];
                b[nt][1] = Wt[n * SM_STRIDE + c + 4];
            }
#pragma unroll
            for (int mt = 0; mt < 4; mt++)
#pragma unroll
                for (int nt = 0; nt < 4; nt++)
                    mma_tf32(acc[mt][nt], a[mt], b[nt]);
        }
    }

    // ---- epilogue: bias + relu + float2 stores ----
#pragma unroll
    for (int mt = 0; mt < 4; mt++) {
#pragma unroll
        for (int nt = 0; nt < 4; nt++) {
            int r0 = row0 + warp_m * 64 + mt * 16 + (lane >> 2);
            int c0 = warp_n * 32 + nt * 8 + 2 * (lane & 3);
            float2 bias = __ldg((const float2*)(b_l + c0));
            if (r0 < NN) {
                float2 o;
                o.x = fmaxf(acc[mt][nt][0] + bias.x, 0.f);
                o.y = fmaxf(acc[mt][nt][1] + bias.y, 0.f);
                *(float2*)(out + (size_t)r0 * C + c0) = o;
            }
            int r1 = r0 + 8;
            if (r1 < NN) {
                float2 o;
                o.x = fmaxf(acc[mt][nt][2] + bias.x, 0.f);
                o.y = fmaxf(acc[mt][nt][3] + bias.y, 0.f);
                *(float2*)(out + (size_t)r1 * C + c0) = o;
            }
        }
    }
}

// ---------------------------------------------------------------------------
// Launch
// ---------------------------------------------------------------------------
extern "C" void kernel_launch(void* const* d_in, const int* in_sizes, int n_in,
                              void* d_out, int out_size)
{
    const float* x        = (const float*)d_in[0];
    const int*   edge_row = (const int*)d_in[1];
    const int*   edge_col = (const int*)d_in[2];
    const float* W_l      = (const float*)d_in[3];
    const float* b_l      = (const float*)d_in[4];
    const float* W_r      = (const float*)d_in[5];
    float*       out      = (float*)d_out;

    // 1) zero counters
    zero_cnt_kernel<<<(NN + 255) / 256, 256>>>();

    // 2) invert edge list into per-dst buckets
    fill_kernel<<<(EE + 255) / 256, 256>>>(edge_row, edge_col);

    // 3) gather + mean-aggregate (one warp per node)
    {
        int warps_per_block = 8;   // 256 threads
        int blocks = (NN + warps_per_block - 1) / warps_per_block;
        gather_agg_kernel<<<blocks, 256>>>(x);
    }

    // 4) fused tensor-core GEMM + epilogue
    {
        int blocks = (NN + 127) / 128;
        sage_gemm_kernel<<<blocks, 256>>>(x, W_l, b_l, W_r, out);
    }
}

// round 7
// speedup vs baseline: 2.2196x; 1.5385x over previous
#include <cuda_runtime.h>
#include <cuda_bf16.h>
#include <cstdint>

// Problem constants (fixed by the dataset)
#define NN 100000
#define EE 1600000
#define C  128           // IN_C == OUT_C == 128
#define CAP 96           // max bucket capacity per node (Poisson(16) tail ~1e-16)

// Scratch (no allocations allowed — device globals)
__device__ float g_agg[(size_t)NN * C];        // 51.2 MB mean-aggregated features
__device__ int   g_cnt[NN];                    // per-node degree counters
__device__ int   g_bucket[(size_t)NN * CAP];   // 38.4 MB src-id buckets

// ---------------------------------------------------------------------------
// Helpers
// ---------------------------------------------------------------------------
__device__ __forceinline__ uint32_t f2tf32(float f) {
    uint32_t r;
    asm("cvt.rna.tf32.f32 %0, %1;" : "=r"(r) : "f"(f));
    return r;
}

__device__ __forceinline__ void mma_tf32(float c[4], const uint32_t a[4],
                                         const uint32_t b[2]) {
    asm volatile(
        "mma.sync.aligned.m16n8k8.row.col.f32.tf32.tf32.f32 "
        "{%0,%1,%2,%3}, {%4,%5,%6,%7}, {%8,%9}, {%0,%1,%2,%3};"
        : "+f"(c[0]), "+f"(c[1]), "+f"(c[2]), "+f"(c[3])
        : "r"(a[0]), "r"(a[1]), "r"(a[2]), "r"(a[3]), "r"(b[0]), "r"(b[1]));
}

// ---------------------------------------------------------------------------
// Kernel 1: zero the per-node counters
// ---------------------------------------------------------------------------
__global__ void zero_cnt_kernel() {
    int i = blockIdx.x * blockDim.x + threadIdx.x;
    if (i < NN) g_cnt[i] = 0;
}

// ---------------------------------------------------------------------------
// Kernel 2: bucket fill. One thread per edge.
// ---------------------------------------------------------------------------
__global__ __launch_bounds__(256) void fill_kernel(
    const int* __restrict__ edge_row,   // dst
    const int* __restrict__ edge_col)   // src
{
    int e = blockIdx.x * blockDim.x + threadIdx.x;
    if (e >= EE) return;
    int d   = __ldg(edge_row + e);
    int s   = __ldg(edge_col + e);
    int pos = atomicAdd(g_cnt + d, 1);
    if (pos < CAP) {
        g_bucket[(size_t)d * CAP + pos] = s;
    }
}

// ---------------------------------------------------------------------------
// Kernel 3: gather-aggregate. One warp per node, lane owns a float4.
// ---------------------------------------------------------------------------
__global__ __launch_bounds__(256) void gather_agg_kernel(
    const float* __restrict__ x)
{
    int warp = (blockIdx.x * blockDim.x + threadIdx.x) >> 5;
    int lane = threadIdx.x & 31;
    if (warp >= NN) return;

    int cnt = g_cnt[warp];
    int deg = min(cnt, CAP);

    const int*    bkt = g_bucket + (size_t)warp * CAP;
    const float4* x4  = (const float4*)x;

    float4 acc = make_float4(0.f, 0.f, 0.f, 0.f);
    int j = 0;
    for (; j + 4 <= deg; j += 4) {
        int s0 = __ldg(bkt + j);
        int s1 = __ldg(bkt + j + 1);
        int s2 = __ldg(bkt + j + 2);
        int s3 = __ldg(bkt + j + 3);
        float4 v0 = __ldg(x4 + (size_t)s0 * 32 + lane);
        float4 v1 = __ldg(x4 + (size_t)s1 * 32 + lane);
        float4 v2 = __ldg(x4 + (size_t)s2 * 32 + lane);
        float4 v3 = __ldg(x4 + (size_t)s3 * 32 + lane);
        acc.x += v0.x + v1.x + v2.x + v3.x;
        acc.y += v0.y + v1.y + v2.y + v3.y;
        acc.z += v0.z + v1.z + v2.z + v3.z;
        acc.w += v0.w + v1.w + v2.w + v3.w;
    }
    for (; j < deg; j++) {
        int s = __ldg(bkt + j);
        float4 v = __ldg(x4 + (size_t)s * 32 + lane);
        acc.x += v.x; acc.y += v.y; acc.z += v.z; acc.w += v.w;
    }

    float inv = 1.0f / fmaxf((float)cnt, 1.0f);
    acc.x *= inv; acc.y *= inv; acc.z *= inv; acc.w *= inv;
    ((float4*)g_agg)[(size_t)warp * 32 + lane] = acc;
}

// ---------------------------------------------------------------------------
// Kernel 4: fused tensor-core GEMM
//   out = relu( agg @ W_l  +  x @ W_r  + b_l )   ==  [agg | x] @ [W_l ; W_r]
// CTA: 256 threads (8 warps, 2x4), 128x128 output tile, K in 8 chunks of 32.
// A tile: row-major [r][k], stride 36  -> STS.128 staging, conflict-free LDS
//         (bank = 4*(lane>>2) + (lane&3), all 32 distinct).
// W tile: K-major [k][n], stride 132   -> coalesced STS.128 (NO transpose),
//         B-fragment LDS bank = 4*(lane&3) + (lane>>2), all 32 distinct.
// __launch_bounds__(256,2): <=128 regs -> 2 CTAs/SM, inter-CTA overlap of
// load phases with compute.
// ---------------------------------------------------------------------------
#define A_STRIDE 36
#define W_STRIDE 132

__global__ __launch_bounds__(256, 2) void sage_gemm_kernel(
    const float* __restrict__ x,
    const float* __restrict__ W_l,
    const float* __restrict__ b_l,
    const float* __restrict__ W_r,
    float*       __restrict__ out)
{
    __shared__ uint32_t As[128 * A_STRIDE];   // 18.4 KB, row-major [r][k]
    __shared__ uint32_t Wk[32 * W_STRIDE];    // 16.9 KB, K-major  [k][n]

    const int t      = threadIdx.x;
    const int lane   = t & 31;
    const int warp   = t >> 5;
    const int warp_m = warp >> 2;       // 0..1  -> 64 rows each
    const int warp_n = warp & 3;        // 0..3  -> 32 cols each
    const int row0   = blockIdx.x * 128;

    float acc[4][4][4];
#pragma unroll
    for (int mt = 0; mt < 4; mt++)
#pragma unroll
        for (int nt = 0; nt < 4; nt++)
#pragma unroll
            for (int j = 0; j < 4; j++) acc[mt][nt][j] = 0.f;

#pragma unroll
    for (int kc = 0; kc < 8; kc++) {
        const bool  ph1   = (kc < 4);
        const int   kbase = ph1 ? kc * 32 : (kc - 4) * 32;
        const float* Asrc = ph1 ? g_agg : x;
        const float* Wsrc = ph1 ? W_l : W_r;

        if (kc > 0) __syncthreads();   // previous chunk fully consumed

        // ---- stage A tile: 128 rows x 32 k (1024 float4, 4 per thread) ----
#pragma unroll
        for (int i = 0; i < 4; i++) {
            int f    = t + i * 256;
            int r    = f >> 3;           // row in tile
            int c4   = f & 7;            // float4 within 32-k chunk
            int grow = row0 + r;
            float4 v = make_float4(0.f, 0.f, 0.f, 0.f);
            if (grow < NN) {
                v = __ldg((const float4*)(Asrc + (size_t)grow * C + kbase) + c4);
            }
            uint4 u;
            u.x = f2tf32(v.x); u.y = f2tf32(v.y);
            u.z = f2tf32(v.z); u.w = f2tf32(v.w);
            *(uint4*)(As + r * A_STRIDE + c4 * 4) = u;
        }

        // ---- stage W tile K-major: 32 k x 128 n (1024 float4, 4/thread) ----
#pragma unroll
        for (int i = 0; i < 4; i++) {
            int f    = t + i * 256;
            int kloc = f >> 5;           // 0..31
            int n4   = f & 31;           // float4 along n
            float4 w = __ldg((const float4*)(Wsrc + (size_t)(kbase + kloc) * C) + n4);
            uint4 u;
            u.x = f2tf32(w.x); u.y = f2tf32(w.y);
            u.z = f2tf32(w.z); u.w = f2tf32(w.w);
            *(uint4*)(Wk + kloc * W_STRIDE + n4 * 4) = u;
        }
        __syncthreads();

        // ---- compute: 4 k-steps of 8 ----
#pragma unroll
        for (int ks = 0; ks < 4; ks++) {
            const int kk = ks * 8;
            uint32_t a[4][4], b[4][2];
#pragma unroll
            for (int mt = 0; mt < 4; mt++) {
                int r = warp_m * 64 + mt * 16 + (lane >> 2);
                int c = kk + (lane & 3);
                a[mt][0] = As[r * A_STRIDE + c];
                a[mt][1] = As[(r + 8) * A_STRIDE + c];
                a[mt][2] = As[r * A_STRIDE + c + 4];
                a[mt][3] = As[(r + 8) * A_STRIDE + c + 4];
            }
#pragma unroll
            for (int nt = 0; nt < 4; nt++) {
                int n = warp_n * 32 + nt * 8 + (lane >> 2);
                int kr = kk + (lane & 3);
                b[nt][0] = Wk[kr * W_STRIDE + n];
                b[nt][1] = Wk[(kr + 4) * W_STRIDE + n];
            }
#pragma unroll
            for (int mt = 0; mt < 4; mt++)
#pragma unroll
                for (int nt = 0; nt < 4; nt++)
                    mma_tf32(acc[mt][nt], a[mt], b[nt]);
        }
    }

    // ---- epilogue: bias + relu + float2 stores ----
#pragma unroll
    for (int nt = 0; nt < 4; nt++) {
        int c0 = warp_n * 32 + nt * 8 + 2 * (lane & 3);
        float2 bias = __ldg((const float2*)(b_l + c0));
#pragma unroll
        for (int mt = 0; mt < 4; mt++) {
            int r0 = row0 + warp_m * 64 + mt * 16 + (lane >> 2);
            if (r0 < NN) {
                float2 o;
                o.x = fmaxf(acc[mt][nt][0] + bias.x, 0.f);
                o.y = fmaxf(acc[mt][nt][1] + bias.y, 0.f);
                *(float2*)(out + (size_t)r0 * C + c0) = o;
            }
            int r1 = r0 + 8;
            if (r1 < NN) {
                float2 o;
                o.x = fmaxf(acc[mt][nt][2] + bias.x, 0.f);
                o.y = fmaxf(acc[mt][nt][3] + bias.y, 0.f);
                *(float2*)(out + (size_t)r1 * C + c0) = o;
            }
        }
    }
}

// ---------------------------------------------------------------------------
// Launch
// ---------------------------------------------------------------------------
extern "C" void kernel_launch(void* const* d_in, const int* in_sizes, int n_in,
                              void* d_out, int out_size)
{
    const float* x        = (const float*)d_in[0];
    const int*   edge_row = (const int*)d_in[1];
    const int*   edge_col = (const int*)d_in[2];
    const float* W_l      = (const float*)d_in[3];
    const float* b_l      = (const float*)d_in[4];
    const float* W_r      = (const float*)d_in[5];
    float*       out      = (float*)d_out;

    // 1) zero counters
    zero_cnt_kernel<<<(NN + 255) / 256, 256>>>();

    // 2) invert edge list into per-dst buckets
    fill_kernel<<<(EE + 255) / 256, 256>>>(edge_row, edge_col);

    // 3) gather + mean-aggregate (one warp per node)
    {
        int warps_per_block = 8;   // 256 threads
        int blocks = (NN + warps_per_block - 1) / warps_per_block;
        gather_agg_kernel<<<blocks, 256>>>(x);
    }

    // 4) fused tensor-core GEMM + epilogue
    {
        int blocks = (NN + 127) / 128;
        sage_gemm_kernel<<<blocks, 256>>>(x, W_l, b_l, W_r, out);
    }
}

// round 8
// speedup vs baseline: 2.5923x; 1.1679x over previous
#include <cuda_runtime.h>
#include <cuda_bf16.h>
#include <cstdint>

// Problem constants (fixed by the dataset)
#define NN 100000
#define EE 1600000
#define C  128           // IN_C == OUT_C == 128
#define CAP 96           // max bucket capacity per node (Poisson(16) tail ~1e-16)

// Scratch (no allocations allowed — device globals)
__device__ float g_agg[(size_t)NN * C];        // 51.2 MB mean-aggregated features
__device__ int   g_cnt[NN];                    // per-node degree counters
__device__ int   g_bucket[(size_t)NN * CAP];   // 38.4 MB src-id buckets

// ---------------------------------------------------------------------------
// Helpers
// ---------------------------------------------------------------------------
__device__ __forceinline__ uint32_t f2tf32(float f) {
    uint32_t r;
    asm("cvt.rna.tf32.f32 %0, %1;" : "=r"(r) : "f"(f));
    return r;
}

__device__ __forceinline__ void mma_tf32(float c[4], const uint32_t a[4],
                                         const uint32_t b[2]) {
    asm volatile(
        "mma.sync.aligned.m16n8k8.row.col.f32.tf32.tf32.f32 "
        "{%0,%1,%2,%3}, {%4,%5,%6,%7}, {%8,%9}, {%0,%1,%2,%3};"
        : "+f"(c[0]), "+f"(c[1]), "+f"(c[2]), "+f"(c[3])
        : "r"(a[0]), "r"(a[1]), "r"(a[2]), "r"(a[3]), "r"(b[0]), "r"(b[1]));
}

// ---------------------------------------------------------------------------
// Kernel 1: zero the per-node counters
// ---------------------------------------------------------------------------
__global__ void zero_cnt_kernel() {
    int i = blockIdx.x * blockDim.x + threadIdx.x;
    if (i < NN) g_cnt[i] = 0;
}

// ---------------------------------------------------------------------------
// Kernel 2: bucket fill. One thread per edge.
// ---------------------------------------------------------------------------
__global__ __launch_bounds__(256) void fill_kernel(
    const int* __restrict__ edge_row,   // dst
    const int* __restrict__ edge_col)   // src
{
    int e = blockIdx.x * blockDim.x + threadIdx.x;
    if (e >= EE) return;
    int d   = __ldg(edge_row + e);
    int s   = __ldg(edge_col + e);
    int pos = atomicAdd(g_cnt + d, 1);
    if (pos < CAP) {
        g_bucket[(size_t)d * CAP + pos] = s;
    }
}

// ---------------------------------------------------------------------------
// Kernel 3: gather-aggregate. One warp per node, lane owns a float4.
// ---------------------------------------------------------------------------
__global__ __launch_bounds__(256) void gather_agg_kernel(
    const float* __restrict__ x)
{
    int warp = (blockIdx.x * blockDim.x + threadIdx.x) >> 5;
    int lane = threadIdx.x & 31;
    if (warp >= NN) return;

    int cnt = g_cnt[warp];
    int deg = min(cnt, CAP);

    const int*    bkt = g_bucket + (size_t)warp * CAP;
    const float4* x4  = (const float4*)x;

    float4 acc = make_float4(0.f, 0.f, 0.f, 0.f);
    int j = 0;
    for (; j + 4 <= deg; j += 4) {
        int s0 = __ldg(bkt + j);
        int s1 = __ldg(bkt + j + 1);
        int s2 = __ldg(bkt + j + 2);
        int s3 = __ldg(bkt + j + 3);
        float4 v0 = __ldg(x4 + (size_t)s0 * 32 + lane);
        float4 v1 = __ldg(x4 + (size_t)s1 * 32 + lane);
        float4 v2 = __ldg(x4 + (size_t)s2 * 32 + lane);
        float4 v3 = __ldg(x4 + (size_t)s3 * 32 + lane);
        acc.x += v0.x + v1.x + v2.x + v3.x;
        acc.y += v0.y + v1.y + v2.y + v3.y;
        acc.z += v0.z + v1.z + v2.z + v3.z;
        acc.w += v0.w + v1.w + v2.w + v3.w;
    }
    for (; j < deg; j++) {
        int s = __ldg(bkt + j);
        float4 v = __ldg(x4 + (size_t)s * 32 + lane);
        acc.x += v.x; acc.y += v.y; acc.z += v.z; acc.w += v.w;
    }

    float inv = 1.0f / fmaxf((float)cnt, 1.0f);
    acc.x *= inv; acc.y *= inv; acc.z *= inv; acc.w *= inv;
    ((float4*)g_agg)[(size_t)warp * 32 + lane] = acc;
}

// ---------------------------------------------------------------------------
// Kernel 4: software-pipelined, double-buffered tensor-core GEMM
//   out = relu( agg @ W_l  +  x @ W_r  + b_l )   ==  [agg | x] @ [W_l ; W_r]
// CTA: 512 threads (16 warps, 4x4), 128x128 output tile, K in 8 chunks of 32.
// Warp tile 32x32 = 2x4 m16n8k8 tf32 MMAs per k-step, acc = 32 regs.
// Double-buffered smem (70 KB dynamic): while chunk k computes, chunk k+1
// is prefetched GMEM->regs, then regs->smem after a barrier.
// A tile: [r][k] stride 36  (36%32=4): frag bank = 4*(lane>>2)+(lane&3), bijective.
// W tile: [k][n] stride 136 (136%32=8): frag bank = 8*(lane&3)+(lane>>2), bijective.
// ---------------------------------------------------------------------------
#define A_STRIDE 36
#define W_STRIDE 136
#define A_BUF    (128 * A_STRIDE)     // u32 per buffer
#define W_BUF    (32 * W_STRIDE)

__global__ __launch_bounds__(512) void sage_gemm_kernel(
    const float* __restrict__ x,
    const float* __restrict__ W_l,
    const float* __restrict__ b_l,
    const float* __restrict__ W_r,
    float*       __restrict__ out)
{
    extern __shared__ uint32_t sm[];
    uint32_t* As = sm;                 // 2 buffers
    uint32_t* Wk = sm + 2 * A_BUF;     // 2 buffers

    const int t      = threadIdx.x;
    const int lane   = t & 31;
    const int warp   = t >> 5;
    const int warp_m = warp >> 2;       // 0..3 -> 32 rows each
    const int warp_n = warp & 3;        // 0..3 -> 32 cols each
    const int row0   = blockIdx.x * 128;

    float acc[2][4][4];
#pragma unroll
    for (int mt = 0; mt < 2; mt++)
#pragma unroll
        for (int nt = 0; nt < 4; nt++)
#pragma unroll
            for (int j = 0; j < 4; j++) acc[mt][nt][j] = 0.f;

    // Per-thread staging coordinates (2 float4 of A, 2 float4 of W per chunk)
    // A: f = t + i*512 -> r = f>>3 (row), c4 = f&7 (float4 in 32-k chunk)
    // W: f = t + i*512 -> kloc = f>>5, n4 = f&31
    float4 pa[2], pw[2];

#define LOAD_CHUNK(KC)                                                        \
    {                                                                         \
        const bool   ph1_  = ((KC) < 4);                                      \
        const int    kb_   = ph1_ ? (KC) * 32 : ((KC) - 4) * 32;              \
        const float* Asrc_ = ph1_ ? g_agg : x;                                \
        const float* Wsrc_ = ph1_ ? W_l : W_r;                                \
        _Pragma("unroll")                                                     \
        for (int i = 0; i < 2; i++) {                                         \
            int f = t + i * 512;                                              \
            int r = f >> 3, c4 = f & 7;                                       \
            int grow = row0 + r;                                              \
            pa[i] = make_float4(0.f, 0.f, 0.f, 0.f);                          \
            if (grow < NN)                                                    \
                pa[i] = __ldg((const float4*)(Asrc_ + (size_t)grow * C + kb_) \
                              + c4);                                          \
        }                                                                     \
        _Pragma("unroll")                                                     \
        for (int i = 0; i < 2; i++) {                                         \
            int f = t + i * 512;                                              \
            int kloc = f >> 5, n4 = f & 31;                                   \
            pw[i] = __ldg((const float4*)(Wsrc_ + (size_t)(kb_ + kloc) * C)   \
                          + n4);                                              \
        }                                                                     \
    }

#define STORE_CHUNK(BUF)                                                      \
    {                                                                         \
        uint32_t* Ab = As + (BUF) * A_BUF;                                    \
        uint32_t* Wb = Wk + (BUF) * W_BUF;                                    \
        _Pragma("unroll")                                                     \
        for (int i = 0; i < 2; i++) {                                         \
            int f = t + i * 512;                                              \
            int r = f >> 3, c4 = f & 7;                                       \
            uint4 u;                                                          \
            u.x = f2tf32(pa[i].x); u.y = f2tf32(pa[i].y);                     \
            u.z = f2tf32(pa[i].z); u.w = f2tf32(pa[i].w);                     \
            *(uint4*)(Ab + r * A_STRIDE + c4 * 4) = u;                        \
        }                                                                     \
        _Pragma("unroll")                                                     \
        for (int i = 0; i < 2; i++) {                                         \
            int f = t + i * 512;                                              \
            int kloc = f >> 5, n4 = f & 31;                                   \
            uint4 u;                                                          \
            u.x = f2tf32(pw[i].x); u.y = f2tf32(pw[i].y);                     \
            u.z = f2tf32(pw[i].z); u.w = f2tf32(pw[i].w);                     \
            *(uint4*)(Wb + kloc * W_STRIDE + n4 * 4) = u;                     \
        }                                                                     \
    }

    // Prologue: stage chunk 0 into buffer 0
    LOAD_CHUNK(0);
    STORE_CHUNK(0);
    __syncthreads();

#pragma unroll
    for (int kc = 0; kc < 8; kc++) {
        const int buf = kc & 1;
        if (kc < 7) LOAD_CHUNK(kc + 1);   // prefetch next chunk (LDG in flight)

        // ---- compute chunk kc from buffer buf ----
        const uint32_t* Ab = As + buf * A_BUF;
        const uint32_t* Wb = Wk + buf * W_BUF;
#pragma unroll
        for (int ks = 0; ks < 4; ks++) {
            const int kk = ks * 8;
            uint32_t a[2][4], b[4][2];
#pragma unroll
            for (int mt = 0; mt < 2; mt++) {
                int r = warp_m * 32 + mt * 16 + (lane >> 2);
                int c = kk + (lane & 3);
                a[mt][0] = Ab[r * A_STRIDE + c];
                a[mt][1] = Ab[(r + 8) * A_STRIDE + c];
                a[mt][2] = Ab[r * A_STRIDE + c + 4];
                a[mt][3] = Ab[(r + 8) * A_STRIDE + c + 4];
            }
#pragma unroll
            for (int nt = 0; nt < 4; nt++) {
                int n  = warp_n * 32 + nt * 8 + (lane >> 2);
                int kr = kk + (lane & 3);
                b[nt][0] = Wb[kr * W_STRIDE + n];
                b[nt][1] = Wb[(kr + 4) * W_STRIDE + n];
            }
#pragma unroll
            for (int mt = 0; mt < 2; mt++)
#pragma unroll
                for (int nt = 0; nt < 4; nt++)
                    mma_tf32(acc[mt][nt], a[mt], b[nt]);
        }

        if (kc < 7) {
            __syncthreads();              // all warps done reading buf^1 (chunk kc-1)
            STORE_CHUNK(buf ^ 1);
            __syncthreads();              // staged data visible
        }
    }

#undef LOAD_CHUNK
#undef STORE_CHUNK

    // ---- epilogue: bias + relu + float2 stores ----
#pragma unroll
    for (int nt = 0; nt < 4; nt++) {
        int c0 = warp_n * 32 + nt * 8 + 2 * (lane & 3);
        float2 bias = __ldg((const float2*)(b_l + c0));
#pragma unroll
        for (int mt = 0; mt < 2; mt++) {
            int r0 = row0 + warp_m * 32 + mt * 16 + (lane >> 2);
            if (r0 < NN) {
                float2 o;
                o.x = fmaxf(acc[mt][nt][0] + bias.x, 0.f);
                o.y = fmaxf(acc[mt][nt][1] + bias.y, 0.f);
                *(float2*)(out + (size_t)r0 * C + c0) = o;
            }
            int r1 = r0 + 8;
            if (r1 < NN) {
                float2 o;
                o.x = fmaxf(acc[mt][nt][2] + bias.x, 0.f);
                o.y = fmaxf(acc[mt][nt][3] + bias.y, 0.f);
                *(float2*)(out + (size_t)r1 * C + c0) = o;
            }
        }
    }
}

// ---------------------------------------------------------------------------
// Launch
// ---------------------------------------------------------------------------
extern "C" void kernel_launch(void* const* d_in, const int* in_sizes, int n_in,
                              void* d_out, int out_size)
{
    const float* x        = (const float*)d_in[0];
    const int*   edge_row = (const int*)d_in[1];
    const int*   edge_col = (const int*)d_in[2];
    const float* W_l      = (const float*)d_in[3];
    const float* b_l      = (const float*)d_in[4];
    const float* W_r      = (const float*)d_in[5];
    float*       out      = (float*)d_out;

    // 1) zero counters
    zero_cnt_kernel<<<(NN + 255) / 256, 256>>>();

    // 2) invert edge list into per-dst buckets
    fill_kernel<<<(EE + 255) / 256, 256>>>(edge_row, edge_col);

    // 3) gather + mean-aggregate (one warp per node)
    {
        int warps_per_block = 8;   // 256 threads
        int blocks = (NN + warps_per_block - 1) / warps_per_block;
        gather_agg_kernel<<<blocks, 256>>>(x);
    }

    // 4) pipelined tensor-core GEMM + epilogue
    {
        const int smem_bytes = (2 * A_BUF + 2 * W_BUF) * sizeof(uint32_t); // ~70 KB
        cudaFuncSetAttribute(sage_gemm_kernel,
                             cudaFuncAttributeMaxDynamicSharedMemorySize,
                             smem_bytes);
        int blocks = (NN + 127) / 128;
        sage_gemm_kernel<<<blocks, 512, smem_bytes>>>(x, W_l, b_l, W_r, out);
    }
}

// round 9
// speedup vs baseline: 2.6260x; 1.0130x over previous
#include <cuda_runtime.h>
#include <cuda_bf16.h>
#include <cstdint>

// Problem constants (fixed by the dataset)
#define NN 100000
#define EE 1600000
#define C  128           // IN_C == OUT_C == 128
#define CAP 96           // max bucket capacity per node (Poisson(16) tail ~1e-16)

// Scratch (no allocations allowed — device globals)
__device__ __nv_bfloat16 g_xbf[(size_t)NN * C];    // 25.6 MB bf16 copy of x
__device__ __nv_bfloat16 g_aggbf[(size_t)NN * C];  // 25.6 MB bf16 mean-agg
__device__ int   g_cnt[NN];                        // per-node degree counters
__device__ int   g_bucket[(size_t)NN * CAP];       // 38.4 MB src-id buckets

// ---------------------------------------------------------------------------
// Helpers
// ---------------------------------------------------------------------------
__device__ __forceinline__ uint32_t f2tf32(float f) {
    uint32_t r;
    asm("cvt.rna.tf32.f32 %0, %1;" : "=r"(r) : "f"(f));
    return r;
}

__device__ __forceinline__ void mma_tf32(float c[4], const uint32_t a[4],
                                         const uint32_t b[2]) {
    asm volatile(
        "mma.sync.aligned.m16n8k8.row.col.f32.tf32.tf32.f32 "
        "{%0,%1,%2,%3}, {%4,%5,%6,%7}, {%8,%9}, {%0,%1,%2,%3};"
        : "+f"(c[0]), "+f"(c[1]), "+f"(c[2]), "+f"(c[3])
        : "r"(a[0]), "r"(a[1]), "r"(a[2]), "r"(a[3]), "r"(b[0]), "r"(b[1]));
}

// ---------------------------------------------------------------------------
// Kernel 0: convert x (fp32) -> g_xbf (bf16, RNE); also zero counters.
// ---------------------------------------------------------------------------
__global__ __launch_bounds__(256) void convert_kernel(
    const float* __restrict__ x)
{
    int i = blockIdx.x * blockDim.x + threadIdx.x;   // one float4 per thread
    const int n4 = NN * (C / 4);                      // 3.2M
    if (i < n4) {
        float4 v = __ldg((const float4*)x + i);
        __nv_bfloat162 h0 = __floats2bfloat162_rn(v.x, v.y);
        __nv_bfloat162 h1 = __floats2bfloat162_rn(v.z, v.w);
        uint2 u;
        u.x = *(uint32_t*)&h0;
        u.y = *(uint32_t*)&h1;
        ((uint2*)g_xbf)[i] = u;
    }
    if (i < NN) g_cnt[i] = 0;
}

// ---------------------------------------------------------------------------
// Kernel 2: bucket fill. One thread per edge.
// ---------------------------------------------------------------------------
__global__ __launch_bounds__(256) void fill_kernel(
    const int* __restrict__ edge_row,   // dst
    const int* __restrict__ edge_col)   // src
{
    int e = blockIdx.x * blockDim.x + threadIdx.x;
    if (e >= EE) return;
    int d   = __ldg(edge_row + e);
    int s   = __ldg(edge_col + e);
    int pos = atomicAdd(g_cnt + d, 1);
    if (pos < CAP) {
        g_bucket[(size_t)d * CAP + pos] = s;
    }
}

// ---------------------------------------------------------------------------
// Kernel 3: gather-aggregate in bf16. One warp per node, lane owns 4 channels
// (8 bytes). Accumulate fp32, write mean as bf16.
// ---------------------------------------------------------------------------
__device__ __forceinline__ void acc_bf4(float4& acc, uint2 u) {
    acc.x += __uint_as_float(u.x << 16);
    acc.y += __uint_as_float(u.x & 0xFFFF0000u);
    acc.z += __uint_as_float(u.y << 16);
    acc.w += __uint_as_float(u.y & 0xFFFF0000u);
}

__global__ __launch_bounds__(256) void gather_agg_kernel()
{
    int warp = (blockIdx.x * blockDim.x + threadIdx.x) >> 5;
    int lane = threadIdx.x & 31;
    if (warp >= NN) return;

    int cnt = g_cnt[warp];
    int deg = min(cnt, CAP);

    const int*   bkt = g_bucket + (size_t)warp * CAP;
    const uint2* xb  = (const uint2*)g_xbf;           // 8B = 4 bf16 per lane

    float4 acc = make_float4(0.f, 0.f, 0.f, 0.f);
    int j = 0;
    for (; j + 4 <= deg; j += 4) {
        int s0 = __ldg(bkt + j);
        int s1 = __ldg(bkt + j + 1);
        int s2 = __ldg(bkt + j + 2);
        int s3 = __ldg(bkt + j + 3);
        uint2 v0 = __ldg(xb + (size_t)s0 * 32 + lane);
        uint2 v1 = __ldg(xb + (size_t)s1 * 32 + lane);
        uint2 v2 = __ldg(xb + (size_t)s2 * 32 + lane);
        uint2 v3 = __ldg(xb + (size_t)s3 * 32 + lane);
        acc_bf4(acc, v0); acc_bf4(acc, v1);
        acc_bf4(acc, v2); acc_bf4(acc, v3);
    }
    for (; j < deg; j++) {
        int s = __ldg(bkt + j);
        uint2 v = __ldg(xb + (size_t)s * 32 + lane);
        acc_bf4(acc, v);
    }

    float inv = 1.0f / fmaxf((float)cnt, 1.0f);
    __nv_bfloat162 h0 = __floats2bfloat162_rn(acc.x * inv, acc.y * inv);
    __nv_bfloat162 h1 = __floats2bfloat162_rn(acc.z * inv, acc.w * inv);
    uint2 o;
    o.x = *(uint32_t*)&h0;
    o.y = *(uint32_t*)&h1;
    ((uint2*)g_aggbf)[(size_t)warp * 32 + lane] = o;
}

// ---------------------------------------------------------------------------
// Kernel 4: software-pipelined, double-buffered tensor-core GEMM
//   out = relu( agg @ W_l  +  x @ W_r  + b_l )   ==  [agg | x] @ [W_l ; W_r]
// CTA: 512 threads (16 warps, 4x4), 128x128 output tile, K in 8 chunks of 32.
// Chunks 0-3: A = g_aggbf (bf16; bf16->tf32 is an exact bit shift).
// Chunks 4-7: A = x (fp32 -> RNA tf32).
// A tile: [r][k] stride 36; W tile: [k][n] stride 136 (both bijective banks).
// ---------------------------------------------------------------------------
#define A_STRIDE 36
#define W_STRIDE 136
#define A_BUF    (128 * A_STRIDE)     // u32 per buffer
#define W_BUF    (32 * W_STRIDE)

__global__ __launch_bounds__(512) void sage_gemm_kernel(
    const float* __restrict__ x,
    const float* __restrict__ W_l,
    const float* __restrict__ b_l,
    const float* __restrict__ W_r,
    float*       __restrict__ out)
{
    extern __shared__ uint32_t sm[];
    uint32_t* As = sm;                 // 2 buffers
    uint32_t* Wk = sm + 2 * A_BUF;     // 2 buffers

    const int t      = threadIdx.x;
    const int lane   = t & 31;
    const int warp   = t >> 5;
    const int warp_m = warp >> 2;       // 0..3 -> 32 rows each
    const int warp_n = warp & 3;        // 0..3 -> 32 cols each
    const int row0   = blockIdx.x * 128;

    float acc[2][4][4];
#pragma unroll
    for (int mt = 0; mt < 2; mt++)
#pragma unroll
        for (int nt = 0; nt < 4; nt++)
#pragma unroll
            for (int j = 0; j < 4; j++) acc[mt][nt][j] = 0.f;

    // Prefetch registers:
    //   bf16 chunks: pabf (one uint4 = 8 bf16; 512 thr * 16B = 8KB tile)
    //   fp32 chunks: pa[2] (two float4; 512 thr * 32B = 16KB tile)
    float4 pa[2];
    uint4  pabf;
    float4 pw[2];

#define LOAD_CHUNK(KC)                                                        \
    {                                                                         \
        const bool   ph1_  = ((KC) < 4);                                      \
        const int    kb_   = ph1_ ? (KC) * 32 : ((KC) - 4) * 32;              \
        const float* Wsrc_ = ph1_ ? W_l : W_r;                                \
        if (ph1_) {                                                           \
            int r = t >> 2, q = t & 3;                                        \
            int grow = row0 + r;                                              \
            pabf = make_uint4(0, 0, 0, 0);                                    \
            if (grow < NN)                                                    \
                pabf = __ldg((const uint4*)(g_aggbf + (size_t)grow * C + kb_) \
                             + q);                                            \
        } else {                                                              \
            _Pragma("unroll")                                                 \
            for (int i = 0; i < 2; i++) {                                     \
                int f = t + i * 512;                                          \
                int r = f >> 3, c4 = f & 7;                                   \
                int grow = row0 + r;                                          \
                pa[i] = make_float4(0.f, 0.f, 0.f, 0.f);                      \
                if (grow < NN)                                                \
                    pa[i] = __ldg((const float4*)(x + (size_t)grow * C + kb_) \
                                  + c4);                                      \
            }                                                                 \
        }                                                                     \
        _Pragma("unroll")                                                     \
        for (int i = 0; i < 2; i++) {                                         \
            int f = t + i * 512;                                              \
            int kloc = f >> 5, n4 = f & 31;                                   \
            pw[i] = __ldg((const float4*)(Wsrc_ + (size_t)(kb_ + kloc) * C)   \
                          + n4);                                              \
        }                                                                     \
    }

#define STORE_CHUNK(BUF, PH1)                                                 \
    {                                                                         \
        uint32_t* Ab = As + (BUF) * A_BUF;                                    \
        uint32_t* Wb = Wk + (BUF) * W_BUF;                                    \
        if (PH1) {                                                            \
            int r = t >> 2, q = t & 3;                                        \
            uint4 u0, u1;                                                     \
            u0.x = pabf.x << 16; u0.y = pabf.x & 0xFFFF0000u;                 \
            u0.z = pabf.y << 16; u0.w = pabf.y & 0xFFFF0000u;                 \
            u1.x = pabf.z << 16; u1.y = pabf.z & 0xFFFF0000u;                 \
            u1.z = pabf.w << 16; u1.w = pabf.w & 0xFFFF0000u;                 \
            *(uint4*)(Ab + r * A_STRIDE + q * 8)     = u0;                    \
            *(uint4*)(Ab + r * A_STRIDE + q * 8 + 4) = u1;                    \
        } else {                                                              \
            _Pragma("unroll")                                                 \
            for (int i = 0; i < 2; i++) {                                     \
                int f = t + i * 512;                                          \
                int r = f >> 3, c4 = f & 7;                                   \
                uint4 u;                                                      \
                u.x = f2tf32(pa[i].x); u.y = f2tf32(pa[i].y);                 \
                u.z = f2tf32(pa[i].z); u.w = f2tf32(pa[i].w);                 \
                *(uint4*)(Ab + r * A_STRIDE + c4 * 4) = u;                    \
            }                                                                 \
        }                                                                     \
        _Pragma("unroll")                                                     \
        for (int i = 0; i < 2; i++) {                                         \
            int f = t + i * 512;                                              \
            int kloc = f >> 5, n4 = f & 31;                                   \
            uint4 u;                                                          \
            u.x = f2tf32(pw[i].x); u.y = f2tf32(pw[i].y);                     \
            u.z = f2tf32(pw[i].z); u.w = f2tf32(pw[i].w);                     \
            *(uint4*)(Wb + kloc * W_STRIDE + n4 * 4) = u;                     \
        }                                                                     \
    }

    // Prologue: stage chunk 0 into buffer 0
    LOAD_CHUNK(0);
    STORE_CHUNK(0, true);
    __syncthreads();

#pragma unroll
    for (int kc = 0; kc < 8; kc++) {
        const int buf = kc & 1;
        if (kc < 7) LOAD_CHUNK(kc + 1);   // prefetch next chunk (LDG in flight)

        // ---- compute chunk kc from buffer buf ----
        const uint32_t* Ab = As + buf * A_BUF;
        const uint32_t* Wb = Wk + buf * W_BUF;
#pragma unroll
        for (int ks = 0; ks < 4; ks++) {
            const int kk = ks * 8;
            uint32_t a[2][4], b[4][2];
#pragma unroll
            for (int mt = 0; mt < 2; mt++) {
                int r = warp_m * 32 + mt * 16 + (lane >> 2);
                int c = kk + (lane & 3);
                a[mt][0] = Ab[r * A_STRIDE + c];
                a[mt][1] = Ab[(r + 8) * A_STRIDE + c];
                a[mt][2] = Ab[r * A_STRIDE + c + 4];
                a[mt][3] = Ab[(r + 8) * A_STRIDE + c + 4];
            }
#pragma unroll
            for (int nt = 0; nt < 4; nt++) {
                int n  = warp_n * 32 + nt * 8 + (lane >> 2);
                int kr = kk + (lane & 3);
                b[nt][0] = Wb[kr * W_STRIDE + n];
                b[nt][1] = Wb[(kr + 4) * W_STRIDE + n];
            }
#pragma unroll
            for (int mt = 0; mt < 2; mt++)
#pragma unroll
                for (int nt = 0; nt < 4; nt++)
                    mma_tf32(acc[mt][nt], a[mt], b[nt]);
        }

        if (kc < 7) {
            __syncthreads();              // all warps done reading buf^1
            STORE_CHUNK(buf ^ 1, (kc + 1) < 4);
            __syncthreads();              // staged data visible
        }
    }

#undef LOAD_CHUNK
#undef STORE_CHUNK

    // ---- epilogue: bias + relu + float2 stores ----
#pragma unroll
    for (int nt = 0; nt < 4; nt++) {
        int c0 = warp_n * 32 + nt * 8 + 2 * (lane & 3);
        float2 bias = __ldg((const float2*)(b_l + c0));
#pragma unroll
        for (int mt = 0; mt < 2; mt++) {
            int r0 = row0 + warp_m * 32 + mt * 16 + (lane >> 2);
            if (r0 < NN) {
                float2 o;
                o.x = fmaxf(acc[mt][nt][0] + bias.x, 0.f);
                o.y = fmaxf(acc[mt][nt][1] + bias.y, 0.f);
                *(float2*)(out + (size_t)r0 * C + c0) = o;
            }
            int r1 = r0 + 8;
            if (r1 < NN) {
                float2 o;
                o.x = fmaxf(acc[mt][nt][2] + bias.x, 0.f);
                o.y = fmaxf(acc[mt][nt][3] + bias.y, 0.f);
                *(float2*)(out + (size_t)r1 * C + c0) = o;
            }
        }
    }
}

// ---------------------------------------------------------------------------
// Launch
// ---------------------------------------------------------------------------
extern "C" void kernel_launch(void* const* d_in, const int* in_sizes, int n_in,
                              void* d_out, int out_size)
{
    const float* x        = (const float*)d_in[0];
    const int*   edge_row = (const int*)d_in[1];
    const int*   edge_col = (const int*)d_in[2];
    const float* W_l      = (const float*)d_in[3];
    const float* b_l      = (const float*)d_in[4];
    const float* W_r      = (const float*)d_in[5];
    float*       out      = (float*)d_out;

    // 1) convert x -> bf16, zero counters
    {
        int n4 = NN * (C / 4);
        convert_kernel<<<(n4 + 255) / 256, 256>>>(x);
    }

    // 2) invert edge list into per-dst buckets
    fill_kernel<<<(EE + 255) / 256, 256>>>(edge_row, edge_col);

    // 3) gather + mean-aggregate in bf16 (one warp per node)
    {
        int warps_per_block = 8;   // 256 threads
        int blocks = (NN + warps_per_block - 1) / warps_per_block;
        gather_agg_kernel<<<blocks, 256>>>();
    }

    // 4) pipelined tensor-core GEMM + epilogue
    {
        const int smem_bytes = (2 * A_BUF + 2 * W_BUF) * sizeof(uint32_t); // ~70 KB
        cudaFuncSetAttribute(sage_gemm_kernel,
                             cudaFuncAttributeMaxDynamicSharedMemorySize,
                             smem_bytes);
        int blocks = (NN + 127) / 128;
        sage_gemm_kernel<<<blocks, 512, smem_bytes>>>(x, W_l, b_l, W_r, out);
    }
}

// round 10
// speedup vs baseline: 2.7051x; 1.0301x over previous
#include <cuda_runtime.h>
#include <cuda_bf16.h>
#include <cstdint>

// Problem constants (fixed by the dataset)
#define NN 100000
#define EE 1600000
#define C  128           // IN_C == OUT_C == 128
#define CAP 96           // max bucket capacity per node (Poisson(16) tail ~1e-16)

// Scratch (no allocations allowed — device globals)
__device__ __nv_bfloat16 g_xbf[(size_t)NN * C];    // 25.6 MB bf16 copy of x
__device__ __nv_bfloat16 g_aggbf[(size_t)NN * C];  // 25.6 MB bf16 mean-agg
__device__ int   g_cnt[NN];                        // per-node degree counters
__device__ int   g_bucket[(size_t)NN * CAP];       // 38.4 MB src-id buckets
__device__ uint32_t g_wl_tf[C * C];                // W_l pre-converted to tf32 bits
__device__ uint32_t g_wr_tf[C * C];                // W_r pre-converted to tf32 bits

// ---------------------------------------------------------------------------
// Helpers
// ---------------------------------------------------------------------------
__device__ __forceinline__ uint32_t f2tf32(float f) {
    uint32_t r;
    asm("cvt.rna.tf32.f32 %0, %1;" : "=r"(r) : "f"(f));
    return r;
}

__device__ __forceinline__ void mma_tf32(float c[4], const uint32_t a[4],
                                         const uint32_t b[2]) {
    asm volatile(
        "mma.sync.aligned.m16n8k8.row.col.f32.tf32.tf32.f32 "
        "{%0,%1,%2,%3}, {%4,%5,%6,%7}, {%8,%9}, {%0,%1,%2,%3};"
        : "+f"(c[0]), "+f"(c[1]), "+f"(c[2]), "+f"(c[3])
        : "r"(a[0]), "r"(a[1]), "r"(a[2]), "r"(a[3]), "r"(b[0]), "r"(b[1]));
}

__device__ __forceinline__ void cp_async16(uint32_t smem_addr, const void* gptr) {
    asm volatile("cp.async.cg.shared.global [%0], [%1], 16;"
                 :: "r"(smem_addr), "l"(gptr));
}
__device__ __forceinline__ void cp_async_commit() {
    asm volatile("cp.async.commit_group;");
}
__device__ __forceinline__ void cp_async_wait0() {
    asm volatile("cp.async.wait_group 0;");
}

// ---------------------------------------------------------------------------
// Kernel 0: convert x -> bf16, W_l/W_r -> tf32 bits; zero counters.
// ---------------------------------------------------------------------------
__global__ __launch_bounds__(256) void convert_kernel(
    const float* __restrict__ x,
    const float* __restrict__ W_l,
    const float* __restrict__ W_r)
{
    int i = blockIdx.x * blockDim.x + threadIdx.x;   // one float4 per thread
    const int n4 = NN * (C / 4);                      // 3.2M
    if (i < n4) {
        float4 v = __ldg((const float4*)x + i);
        __nv_bfloat162 h0 = __floats2bfloat162_rn(v.x, v.y);
        __nv_bfloat162 h1 = __floats2bfloat162_rn(v.z, v.w);
        uint2 u;
        u.x = *(uint32_t*)&h0;
        u.y = *(uint32_t*)&h1;
        ((uint2*)g_xbf)[i] = u;
    }
    if (i < C * C / 4) {  // 4096 float4 per weight matrix
        float4 wl = __ldg((const float4*)W_l + i);
        float4 wr = __ldg((const float4*)W_r + i);
        uint4 ul, ur;
        ul.x = f2tf32(wl.x); ul.y = f2tf32(wl.y);
        ul.z = f2tf32(wl.z); ul.w = f2tf32(wl.w);
        ur.x = f2tf32(wr.x); ur.y = f2tf32(wr.y);
        ur.z = f2tf32(wr.z); ur.w = f2tf32(wr.w);
        ((uint4*)g_wl_tf)[i] = ul;
        ((uint4*)g_wr_tf)[i] = ur;
    }
    if (i < NN) g_cnt[i] = 0;
}

// ---------------------------------------------------------------------------
// Kernel 2: bucket fill. One thread per edge.
// ---------------------------------------------------------------------------
__global__ __launch_bounds__(256) void fill_kernel(
    const int* __restrict__ edge_row,   // dst
    const int* __restrict__ edge_col)   // src
{
    int e = blockIdx.x * blockDim.x + threadIdx.x;
    if (e >= EE) return;
    int d   = __ldg(edge_row + e);
    int s   = __ldg(edge_col + e);
    int pos = atomicAdd(g_cnt + d, 1);
    if (pos < CAP) {
        g_bucket[(size_t)d * CAP + pos] = s;
    }
}

// ---------------------------------------------------------------------------
// Kernel 3: gather-aggregate in bf16. One warp per node.
// Indices preloaded lane-parallel (1-3 coalesced LDG), broadcast via shfl.
// Feature loads issued 8 at a time (MLP=8) to hide L2 latency.
// ---------------------------------------------------------------------------
__device__ __forceinline__ void acc_bf4(float4& acc, uint2 u) {
    acc.x += __uint_as_float(u.x << 16);
    acc.y += __uint_as_float(u.x & 0xFFFF0000u);
    acc.z += __uint_as_float(u.y << 16);
    acc.w += __uint_as_float(u.y & 0xFFFF0000u);
}

__global__ __launch_bounds__(256) void gather_agg_kernel()
{
    int warp = (blockIdx.x * blockDim.x + threadIdx.x) >> 5;
    int lane = threadIdx.x & 31;
    if (warp >= NN) return;

    int cnt = g_cnt[warp];
    int deg = min(cnt, CAP);

    const int*   bkt = g_bucket + (size_t)warp * CAP;
    const uint2* xb  = (const uint2*)g_xbf;           // 8B = 4 bf16 per lane

    // Lane-parallel index preload (covers up to CAP=96)
    int i0 = (lane      < deg) ? __ldg(bkt + lane)      : 0;
    int i1 = (lane + 32 < deg) ? __ldg(bkt + lane + 32) : 0;
    int i2 = (lane + 64 < deg) ? __ldg(bkt + lane + 64) : 0;

    float4 acc = make_float4(0.f, 0.f, 0.f, 0.f);

    int j = 0;
    for (; j + 8 <= deg; j += 8) {
        int s[8];
#pragma unroll
        for (int u = 0; u < 8; u++) {
            int jj = j + u;
            int r  = (jj < 32) ? i0 : ((jj < 64) ? i1 : i2);
            s[u] = __shfl_sync(0xffffffffu, r, jj & 31);
        }
        uint2 v[8];
#pragma unroll
        for (int u = 0; u < 8; u++)
            v[u] = __ldg(xb + (size_t)s[u] * 32 + lane);
#pragma unroll
        for (int u = 0; u < 8; u++)
            acc_bf4(acc, v[u]);
    }
    for (; j < deg; j++) {
        int r = (j < 32) ? i0 : ((j < 64) ? i1 : i2);
        int s = __shfl_sync(0xffffffffu, r, j & 31);
        uint2 v = __ldg(xb + (size_t)s * 32 + lane);
        acc_bf4(acc, v);
    }

    float inv = 1.0f / fmaxf((float)cnt, 1.0f);
    __nv_bfloat162 h0 = __floats2bfloat162_rn(acc.x * inv, acc.y * inv);
    __nv_bfloat162 h1 = __floats2bfloat162_rn(acc.z * inv, acc.w * inv);
    uint2 o;
    o.x = *(uint32_t*)&h0;
    o.y = *(uint32_t*)&h1;
    ((uint2*)g_aggbf)[(size_t)warp * 32 + lane] = o;
}

// ---------------------------------------------------------------------------
// Kernel 4: double-buffered tensor-core GEMM, 256 threads, 2 CTAs/SM.
//   out = relu( agg @ W_l + x @ W_r + b_l )  ==  [agg | x] @ [W_l ; W_r]
// 8 warps (2x4), warp tile 64x32, acc[4][4][4] = 64 regs.
// W staged via cp.async from pre-converted tf32 copies (no W regs, no W STS).
// A staged via register prefetch (bf16 agg chunks: shift-expand; fp32 x: cvt).
// One __syncthreads per chunk; 2 resident CTAs overlap staging with compute.
// ---------------------------------------------------------------------------
#define A_STRIDE 36
#define W_STRIDE 136
#define A_BUF    (128 * A_STRIDE)     // u32 per buffer
#define W_BUF    (32 * W_STRIDE)

__global__ __launch_bounds__(256, 2) void sage_gemm_kernel(
    const float* __restrict__ x,
    const float* __restrict__ b_l,
    float*       __restrict__ out)
{
    extern __shared__ uint32_t sm[];
    uint32_t* As = sm;                 // 2 buffers
    uint32_t* Wk = sm + 2 * A_BUF;     // 2 buffers

    const int t      = threadIdx.x;
    const int lane   = t & 31;
    const int warp   = t >> 5;
    const int warp_m = warp >> 2;       // 0..1 -> 64 rows each
    const int warp_n = warp & 3;        // 0..3 -> 32 cols each
    const int row0   = blockIdx.x * 128;

    float acc[4][4][4];
#pragma unroll
    for (int mt = 0; mt < 4; mt++)
#pragma unroll
        for (int nt = 0; nt < 4; nt++)
#pragma unroll
            for (int j = 0; j < 4; j++) acc[mt][nt][j] = 0.f;

    float4 pa[4];     // fp32 x chunk prefetch (4 float4)
    uint4  pabf[2];   // bf16 agg chunk prefetch (2 uint4)

#define CP_W(KC, BUF)                                                         \
    {                                                                         \
        const uint32_t* Wsrc_ =                                               \
            (((KC) < 4) ? g_wl_tf : g_wr_tf) + ((KC) & 3) * 32 * C;           \
        uint32_t* Wb_ = Wk + (BUF) * W_BUF;                                   \
        _Pragma("unroll")                                                     \
        for (int i = 0; i < 4; i++) {                                         \
            int f = t + i * 256;                                              \
            int kloc = f >> 5, n4 = f & 31;                                   \
            uint32_t dst = (uint32_t)__cvta_generic_to_shared(                \
                Wb_ + kloc * W_STRIDE + n4 * 4);                              \
            cp_async16(dst, Wsrc_ + kloc * C + n4 * 4);                       \
        }                                                                     \
        cp_async_commit();                                                    \
    }

#define LOAD_A(KC)                                                            \
    {                                                                         \
        if ((KC) < 4) {                                                       \
            const int kb_ = (KC) * 32;                                        \
            _Pragma("unroll")                                                 \
            for (int i = 0; i < 2; i++) {                                     \
                int f = t + i * 256;                                          \
                int r = f >> 2, q = f & 3;                                    \
                int grow = row0 + r;                                          \
                pabf[i] = make_uint4(0, 0, 0, 0);                             \
                if (grow < NN)                                                \
                    pabf[i] = __ldg(                                          \
                        (const uint4*)(g_aggbf + (size_t)grow * C + kb_) + q);\
            }                                                                 \
        } else {                                                              \
            const int kb_ = ((KC) - 4) * 32;                                  \
            _Pragma("unroll")                                                 \
            for (int i = 0; i < 4; i++) {                                     \
                int f = t + i * 256;                                          \
                int r = f >> 3, c4 = f & 7;                                   \
                int grow = row0 + r;                                          \
                pa[i] = make_float4(0.f, 0.f, 0.f, 0.f);                      \
                if (grow < NN)                                                \
                    pa[i] = __ldg(                                            \
                        (const float4*)(x + (size_t)grow * C + kb_) + c4);    \
            }                                                                 \
        }                                                                     \
    }

#define STORE_A(KC, BUF)                                                      \
    {                                                                         \
        uint32_t* Ab_ = As + (BUF) * A_BUF;                                   \
        if ((KC) < 4) {                                                       \
            _Pragma("unroll")                                                 \
            for (int i = 0; i < 2; i++) {                                     \
                int f = t + i * 256;                                          \
                int r = f >> 2, q = f & 3;                                    \
                uint4 u0, u1;                                                 \
                u0.x = pabf[i].x << 16; u0.y = pabf[i].x & 0xFFFF0000u;       \
                u0.z = pabf[i].y << 16; u0.w = pabf[i].y & 0xFFFF0000u;       \
                u1.x = pabf[i].z << 16; u1.y = pabf[i].z & 0xFFFF0000u;       \
                u1.z = pabf[i].w << 16; u1.w = pabf[i].w & 0xFFFF0000u;       \
                *(uint4*)(Ab_ + r * A_STRIDE + q * 8)     = u0;               \
                *(uint4*)(Ab_ + r * A_STRIDE + q * 8 + 4) = u1;               \
            }                                                                 \
        } else {                                                              \
            _Pragma("unroll")                                                 \
            for (int i = 0; i < 4; i++) {                                     \
                int f = t + i * 256;                                          \
                int r = f >> 3, c4 = f & 7;                                   \
                uint4 u;                                                      \
                u.x = f2tf32(pa[i].x); u.y = f2tf32(pa[i].y);                 \
                u.z = f2tf32(pa[i].z); u.w = f2tf32(pa[i].w);                 \
                *(uint4*)(Ab_ + r * A_STRIDE + c4 * 4) = u;                   \
            }                                                                 \
        }                                                                     \
    }

    // Prologue: stage chunk 0 into buffer 0
    CP_W(0, 0);
    LOAD_A(0);
    STORE_A(0, 0);
    cp_async_wait0();
    __syncthreads();

#pragma unroll
    for (int kc = 0; kc < 8; kc++) {
        const int buf = kc & 1;
        if (kc < 7) {
            CP_W(kc + 1, buf ^ 1);   // async into the other buffer
            LOAD_A(kc + 1);          // LDG in flight during compute
        }

        // ---- compute chunk kc from buffer buf ----
        const uint32_t* Ab = As + buf * A_BUF;
        const uint32_t* Wb = Wk + buf * W_BUF;
#pragma unroll
        for (int ks = 0; ks < 4; ks++) {
            const int kk = ks * 8;
            uint32_t a[4][4], b[4][2];
#pragma unroll
            for (int mt = 0; mt < 4; mt++) {
                int r = warp_m * 64 + mt * 16 + (lane >> 2);
                int c = kk + (lane & 3);
                a[mt][0] = Ab[r * A_STRIDE + c];
                a[mt][1] = Ab[(r + 8) * A_STRIDE + c];
                a[mt][2] = Ab[r * A_STRIDE + c + 4];
                a[mt][3] = Ab[(r + 8) * A_STRIDE + c + 4];
            }
#pragma unroll
            for (int nt = 0; nt < 4; nt++) {
                int n  = warp_n * 32 + nt * 8 + (lane >> 2);
                int kr = kk + (lane & 3);
                b[nt][0] = Wb[kr * W_STRIDE + n];
                b[nt][1] = Wb[(kr + 4) * W_STRIDE + n];
            }
#pragma unroll
            for (int mt = 0; mt < 4; mt++)
#pragma unroll
                for (int nt = 0; nt < 4; nt++)
                    mma_tf32(acc[mt][nt], a[mt], b[nt]);
        }

        if (kc < 7) {
            // buf^1 was last read in chunk kc-1 (barrier passed) -> safe to fill
            STORE_A(kc + 1, buf ^ 1);
            cp_async_wait0();
            __syncthreads();
        }
    }

#undef CP_W
#undef LOAD_A
#undef STORE_A

    // ---- epilogue: bias + relu + float2 stores ----
#pragma unroll
    for (int nt = 0; nt < 4; nt++) {
        int c0 = warp_n * 32 + nt * 8 + 2 * (lane & 3);
        float2 bias = __ldg((const float2*)(b_l + c0));
#pragma unroll
        for (int mt = 0; mt < 4; mt++) {
            int r0 = row0 + warp_m * 64 + mt * 16 + (lane >> 2);
            if (r0 < NN) {
                float2 o;
                o.x = fmaxf(acc[mt][nt][0] + bias.x, 0.f);
                o.y = fmaxf(acc[mt][nt][1] + bias.y, 0.f);
                *(float2*)(out + (size_t)r0 * C + c0) = o;
            }
            int r1 = r0 + 8;
            if (r1 < NN) {
                float2 o;
                o.x = fmaxf(acc[mt][nt][2] + bias.x, 0.f);
                o.y = fmaxf(acc[mt][nt][3] + bias.y, 0.f);
                *(float2*)(out + (size_t)r1 * C + c0) = o;
            }
        }
    }
}

// ---------------------------------------------------------------------------
// Launch
// ---------------------------------------------------------------------------
extern "C" void kernel_launch(void* const* d_in, const int* in_sizes, int n_in,
                              void* d_out, int out_size)
{
    const float* x        = (const float*)d_in[0];
    const int*   edge_row = (const int*)d_in[1];
    const int*   edge_col = (const int*)d_in[2];
    const float* W_l      = (const float*)d_in[3];
    const float* b_l      = (const float*)d_in[4];
    const float* W_r      = (const float*)d_in[5];
    float*       out      = (float*)d_out;

    // 1) convert x -> bf16, W -> tf32 bits, zero counters
    {
        int n4 = NN * (C / 4);
        convert_kernel<<<(n4 + 255) / 256, 256>>>(x, W_l, W_r);
    }

    // 2) invert edge list into per-dst buckets
    fill_kernel<<<(EE + 255) / 256, 256>>>(edge_row, edge_col);

    // 3) gather + mean-aggregate in bf16 (one warp per node, MLP=8)
    {
        int warps_per_block = 8;   // 256 threads
        int blocks = (NN + warps_per_block - 1) / warps_per_block;
        gather_agg_kernel<<<blocks, 256>>>();
    }

    // 4) pipelined tensor-core GEMM + epilogue (2 CTAs/SM)
    {
        const int smem_bytes = (2 * A_BUF + 2 * W_BUF) * sizeof(uint32_t); // ~70 KB
        cudaFuncSetAttribute(sage_gemm_kernel,
                             cudaFuncAttributeMaxDynamicSharedMemorySize,
                             smem_bytes);
        int blocks = (NN + 127) / 128;
        sage_gemm_kernel<<<blocks, 256, smem_bytes>>>(x, b_l, out);
    }
}